// round 3
// baseline (speedup 1.0000x reference)
#include <cuda_runtime.h>
#include <cuda_fp16.h>
#include <cstdint>

// ============================================================================
// ScaledDotProductAttention  B=4 H=16 S=2048 D=128, causal, fp32 in/out
// FlashAttention-2 structure with mma.sync.m16n8k16 (family-common HMMA) and
// split-fp16 (hi+lo) 3-pass GEMMs for fp32-grade accuracy.
// NOTE: tcgen05/TMEM is NOT available — harness compiles via compute_103
// (no 'a' feature set), so only family-common tensor instructions work.
// ============================================================================

static constexpr int SEQ = 2048;
static constexpr int DH  = 128;
static constexpr float SCALE = 0.08838834764831845f;  // 1/sqrt(128)

static constexpr int LDH = 136;   // padded SMEM stride in halfs (272B rows)

// SMEM layout (half units)
enum : uint32_t {
    QHI_OFF = 0,
    QLO_OFF = QHI_OFF + 128 * LDH,
    KHI_OFF = QLO_OFF + 128 * LDH,
    KLO_OFF = KHI_OFF + 64 * LDH,
    VHI_OFF = KLO_OFF + 64 * LDH,
    VLO_OFF = VHI_OFF + 64 * LDH,
    SMEM_HALVES = VLO_OFF + 64 * LDH
};
static constexpr uint32_t SMEM_BYTES = SMEM_HALVES * 2;   // 139264

// ---------------------------------------------------------------------------
__device__ __forceinline__ uint32_t cvta_s(const void* p) {
    uint32_t a;
    asm("{ .reg .u64 t; cvta.to.shared.u64 t, %1; cvt.u32.u64 %0, t; }"
        : "=r"(a) : "l"(p));
    return a;
}

__device__ __forceinline__ void ldsm4(uint32_t r[4], uint32_t addr) {
    asm volatile("ldmatrix.sync.aligned.m8n8.x4.shared.b16 {%0,%1,%2,%3}, [%4];"
                 : "=r"(r[0]), "=r"(r[1]), "=r"(r[2]), "=r"(r[3]) : "r"(addr));
}

__device__ __forceinline__ void ldsm4t(uint32_t r[4], uint32_t addr) {
    asm volatile("ldmatrix.sync.aligned.m8n8.x4.trans.shared.b16 {%0,%1,%2,%3}, [%4];"
                 : "=r"(r[0]), "=r"(r[1]), "=r"(r[2]), "=r"(r[3]) : "r"(addr));
}

__device__ __forceinline__ void mma16816(float d[4], const uint32_t a[4],
                                         const uint32_t b[2]) {
    asm volatile(
        "mma.sync.aligned.m16n8k16.row.col.f32.f16.f16.f32 "
        "{%0,%1,%2,%3}, {%4,%5,%6,%7}, {%8,%9}, {%0,%1,%2,%3};"
        : "+f"(d[0]), "+f"(d[1]), "+f"(d[2]), "+f"(d[3])
        : "r"(a[0]), "r"(a[1]), "r"(a[2]), "r"(a[3]), "r"(b[0]), "r"(b[1]));
}

__device__ __forceinline__ uint32_t packh2(float a, float b) {
    __half2 h = __floats2half2_rn(a, b);
    return *reinterpret_cast<uint32_t*>(&h);
}

// store float4 as split hi/lo half2s at tile[row][col..col+3]
__device__ __forceinline__ void store_split(__half* sm, uint32_t offH, uint32_t offL,
                                            int row, int col, float4 v) {
    __half hx = __float2half_rn(v.x), hy = __float2half_rn(v.y);
    __half hz = __float2half_rn(v.z), hw = __float2half_rn(v.w);
    uint32_t p = row * LDH + col;
    *(__half2*)&sm[offH + p]     = __halves2half2(hx, hy);
    *(__half2*)&sm[offH + p + 2] = __halves2half2(hz, hw);
    *(__half2*)&sm[offL + p] =
        __halves2half2(__float2half_rn(v.x - __half2float(hx)),
                       __float2half_rn(v.y - __half2float(hy)));
    *(__half2*)&sm[offL + p + 2] =
        __halves2half2(__float2half_rn(v.z - __half2float(hz)),
                       __float2half_rn(v.w - __half2float(hw)));
}

// ---------------------------------------------------------------------------
__global__ void __launch_bounds__(256, 1)
fa2_hmma_kernel(const float* __restrict__ Qg, const float* __restrict__ Kg,
                const float* __restrict__ Vg, float* __restrict__ Og)
{
    extern __shared__ __half sm[];
    const uint32_t sb = cvta_s(sm);
    const int tid  = threadIdx.x;
    const int w    = tid >> 5;
    const int lane = tid & 31;
    const int g    = lane >> 2;    // row group 0..7
    const int c    = lane & 3;     // col pair 0..3
    const int bh   = blockIdx.x;
    const int qt   = 15 - (int)blockIdx.y;        // heavy q-tiles first
    const size_t base = (size_t)bh * SEQ * DH;
    const int qr0  = qt * 128;

    // ---- per-lane ldmatrix address components (byte addresses) -------------
    // A-frag (Q / 16x16): row = 16w + (lane&7) + ((lane>>3)&1)*8; col = 16s + (lane>>4)*8
    const int a_row = 16 * w + (lane & 7) + ((lane >> 3) & 1) * 8;
    const int a_col8 = (lane >> 4) * 8;
    // B-frag K (pair t: keys 16t..16t+16, kstep s): row = 16t + (lane&7) + (lane>>4)*8;
    //   col = 16s + ((lane>>3)&1)*8
    const int bk_rowi = (lane & 7) + (lane >> 4) * 8;
    const int bk_col8 = ((lane >> 3) & 1) * 8;
    // B-frag V trans (pair t: d cols 16t..16t+16, kstep s): row = 16s + (lane&7) + ((lane>>3)&1)*8;
    //   col = 16t + (lane>>4)*8
    const int bv_rowi = (lane & 7) + ((lane >> 3) & 1) * 8;
    const int bv_col8 = (lane >> 4) * 8;

    // ---- prologue: Q tile -> split fp16 SMEM (pre-scaled) ------------------
    #pragma unroll
    for (int i = 0; i < 16; i++) {
        int idx = tid + i * 256;          // 0..4095
        int row = idx >> 5, c4 = idx & 31;
        float4 v = *(const float4*)(Qg + base + (size_t)(qr0 + row) * DH + 4 * c4);
        v.x *= SCALE; v.y *= SCALE; v.z *= SCALE; v.w *= SCALE;
        store_split(sm, QHI_OFF, QLO_OFF, row, 4 * c4, v);
    }

    float O_[16][4];
    #pragma unroll
    for (int n = 0; n < 16; n++)
        #pragma unroll
        for (int e = 0; e < 4; e++) O_[n][e] = 0.0f;
    float mA = -1e30f, mB = -1e30f, lA = 0.0f, lB = 0.0f;

    const int nkt = 2 * (qt + 1);

    for (int j = 0; j < nkt; j++) {
        __syncthreads();   // previous tile fully consumed (and Q writes on j=0)

        // ---- load K/V 64x128 tile -> split fp16 SMEM -----------------------
        #pragma unroll
        for (int i = 0; i < 8; i++) {
            int idx = tid + i * 256;       // 0..2047
            int row = idx >> 5, c4 = idx & 31;
            size_t goff = base + (size_t)(64 * j + row) * DH + 4 * c4;
            float4 kv = *(const float4*)(Kg + goff);
            store_split(sm, KHI_OFF, KLO_OFF, row, 4 * c4, kv);
            float4 vv = *(const float4*)(Vg + goff);
            store_split(sm, VHI_OFF, VLO_OFF, row, 4 * c4, vv);
        }
        __syncthreads();

        // ---- S = Q K^T  (3-pass split fp16, fp32 accum) --------------------
        float S_[8][4];
        #pragma unroll
        for (int n = 0; n < 8; n++)
            #pragma unroll
            for (int e = 0; e < 4; e++) S_[n][e] = 0.0f;

        #pragma unroll
        for (int s = 0; s < 8; s++) {
            uint32_t qh[4], ql[4];
            uint32_t qa = sb + 2u * (uint32_t)(a_row * LDH + 16 * s + a_col8);
            ldsm4(qh, qa + 2u * QHI_OFF);
            ldsm4(ql, qa + 2u * QLO_OFF);
            #pragma unroll
            for (int t = 0; t < 4; t++) {
                uint32_t bhh[4], bll[4];
                uint32_t ka = sb + 2u * (uint32_t)((16 * t + bk_rowi) * LDH
                                                   + 16 * s + bk_col8);
                ldsm4(bhh, ka + 2u * KHI_OFF);
                ldsm4(bll, ka + 2u * KLO_OFF);
                mma16816(S_[2 * t],     qh, bhh);
                mma16816(S_[2 * t + 1], qh, bhh + 2);
                mma16816(S_[2 * t],     ql, bhh);
                mma16816(S_[2 * t + 1], ql, bhh + 2);
                mma16816(S_[2 * t],     qh, bll);
                mma16816(S_[2 * t + 1], qh, bll + 2);
            }
        }

        // ---- causal mask (only the two diagonal-overlap tiles) -------------
        const int rowA = qr0 + 16 * w + g;
        const int rowB = rowA + 8;
        if (j >= 2 * qt) {
            int kb = 64 * j;
            #pragma unroll
            for (int n = 0; n < 8; n++) {
                #pragma unroll
                for (int e = 0; e < 2; e++) {
                    int key = kb + 8 * n + 2 * c + e;
                    if (key > rowA) S_[n][e]     = -1e30f;
                    if (key > rowB) S_[n][2 + e] = -1e30f;
                }
            }
        }

        // ---- online softmax (quad-local rows) ------------------------------
        float mtA = -1e30f, mtB = -1e30f;
        #pragma unroll
        for (int n = 0; n < 8; n++) {
            mtA = fmaxf(mtA, fmaxf(S_[n][0], S_[n][1]));
            mtB = fmaxf(mtB, fmaxf(S_[n][2], S_[n][3]));
        }
        mtA = fmaxf(mtA, __shfl_xor_sync(0xffffffffu, mtA, 1));
        mtA = fmaxf(mtA, __shfl_xor_sync(0xffffffffu, mtA, 2));
        mtB = fmaxf(mtB, __shfl_xor_sync(0xffffffffu, mtB, 1));
        mtB = fmaxf(mtB, __shfl_xor_sync(0xffffffffu, mtB, 2));

        float mnA = fmaxf(mA, mtA), mnB = fmaxf(mB, mtB);
        float corrA = __expf(mA - mnA), corrB = __expf(mB - mnB);

        float sA = 0.0f, sB = 0.0f;
        #pragma unroll
        for (int n = 0; n < 8; n++) {
            S_[n][0] = __expf(S_[n][0] - mnA);
            S_[n][1] = __expf(S_[n][1] - mnA);
            S_[n][2] = __expf(S_[n][2] - mnB);
            S_[n][3] = __expf(S_[n][3] - mnB);
            sA += S_[n][0] + S_[n][1];
            sB += S_[n][2] + S_[n][3];
        }
        sA += __shfl_xor_sync(0xffffffffu, sA, 1);
        sA += __shfl_xor_sync(0xffffffffu, sA, 2);
        sB += __shfl_xor_sync(0xffffffffu, sB, 1);
        sB += __shfl_xor_sync(0xffffffffu, sB, 2);

        lA = lA * corrA + sA;  mA = mnA;
        lB = lB * corrB + sB;  mB = mnB;

        // ---- rescale O accumulators ---------------------------------------
        #pragma unroll
        for (int n = 0; n < 16; n++) {
            O_[n][0] *= corrA; O_[n][1] *= corrA;
            O_[n][2] *= corrB; O_[n][3] *= corrB;
        }

        // ---- P: C-layout -> A-fragments, split hi/lo -----------------------
        uint32_t ph[4][4], pl[4][4];
        #pragma unroll
        for (int s = 0; s < 4; s++) {
            #pragma unroll
            for (int half_ : {0, 1}) {
                const float* src = S_[2 * s + half_];
                // (c0,c1) -> a0/a2 ; (c2,c3) -> a1/a3
                __half h0 = __float2half_rn(src[0]), h1 = __float2half_rn(src[1]);
                __half h2 = __float2half_rn(src[2]), h3 = __float2half_rn(src[3]);
                ph[s][2 * half_]     = packh2(__half2float(h0), __half2float(h1));
                ph[s][2 * half_ + 1] = packh2(__half2float(h2), __half2float(h3));
                pl[s][2 * half_]     = packh2(src[0] - __half2float(h0),
                                              src[1] - __half2float(h1));
                pl[s][2 * half_ + 1] = packh2(src[2] - __half2float(h2),
                                              src[3] - __half2float(h3));
            }
        }

        // ---- O += P V  (3-pass split) --------------------------------------
        #pragma unroll
        for (int s = 0; s < 4; s++) {
            #pragma unroll
            for (int t = 0; t < 8; t++) {
                uint32_t vh[4], vl[4];
                uint32_t va = sb + 2u * (uint32_t)((16 * s + bv_rowi) * LDH
                                                   + 16 * t + bv_col8);
                ldsm4t(vh, va + 2u * VHI_OFF);
                ldsm4t(vl, va + 2u * VLO_OFF);
                mma16816(O_[2 * t],     ph[s], vh);
                mma16816(O_[2 * t + 1], ph[s], vh + 2);
                mma16816(O_[2 * t],     pl[s], vh);
                mma16816(O_[2 * t + 1], pl[s], vh + 2);
                mma16816(O_[2 * t],     ph[s], vl);
                mma16816(O_[2 * t + 1], ph[s], vl + 2);
            }
        }
    }

    // ---- epilogue: O /= l, store fp32 -------------------------------------
    {
        float iA = 1.0f / lA, iB = 1.0f / lB;
        const int rowA = qr0 + 16 * w + g;
        float* oA = Og + base + (size_t)rowA * DH;
        float* oB = oA + 8 * DH;
        #pragma unroll
        for (int n = 0; n < 16; n++) {
            *(float2*)(oA + 8 * n + 2 * c) =
                make_float2(O_[n][0] * iA, O_[n][1] * iA);
            *(float2*)(oB + 8 * n + 2 * c) =
                make_float2(O_[n][2] * iB, O_[n][3] * iB);
        }
    }
}

// ---------------------------------------------------------------------------
extern "C" void kernel_launch(void* const* d_in, const int* in_sizes, int n_in,
                              void* d_out, int out_size) {
    const float* Q = (const float*)d_in[0];
    const float* K = (const float*)d_in[1];
    const float* V = (const float*)d_in[2];
    // d_in[3] = causal mask (known tril) — applied analytically in-kernel.
    float* O = (float*)d_out;

    cudaFuncSetAttribute(fa2_hmma_kernel,
                         cudaFuncAttributeMaxDynamicSharedMemorySize, SMEM_BYTES);

    dim3 grid(64, 16, 1);   // bh x q-tiles (heavy first via qt = 15 - by)
    fa2_hmma_kernel<<<grid, 256, SMEM_BYTES>>>(Q, K, V, O);
}

// round 4
// speedup vs baseline: 1.3011x; 1.3011x over previous
#include <cuda_runtime.h>
#include <cuda_fp16.h>
#include <cstdint>

// ============================================================================
// ScaledDotProductAttention  B=4 H=16 S=2048 D=128, causal, fp32 in/out
// FlashAttention-2 with mma.sync.m16n8k16 HMMA.
// Precision scheme: Q and P carry split-fp16 (hi+lo, 2 MMA passes per GEMM);
// K and V are single fp16 (their rounding contributes ~2e-4 rel err, well
// under the 1e-3 gate; measured 2.4e-6 with full 3-pass split in R3).
// K/V tiles are double-buffered in SMEM: loads for tile j+1 are issued before
// computing tile j, so DRAM latency overlaps MMA across warps (1 sync/iter).
// ============================================================================

static constexpr int SEQ = 2048;
static constexpr int DH  = 128;
static constexpr float SCALE = 0.08838834764831845f;  // 1/sqrt(128)

static constexpr int LDH = 136;   // padded SMEM stride in halfs

// SMEM layout (half units)
enum : uint32_t {
    QHI_OFF = 0,
    QLO_OFF = QHI_OFF + 128 * LDH,
    KHI_OFF = QLO_OFF + 128 * LDH,     // 2 stages of 64 rows
    VHI_OFF = KHI_OFF + 2 * 64 * LDH,  // 2 stages of 64 rows
    SMEM_HALVES = VHI_OFF + 2 * 64 * LDH
};
static constexpr uint32_t SMEM_BYTES = SMEM_HALVES * 2;   // 139264

// ---------------------------------------------------------------------------
__device__ __forceinline__ uint32_t cvta_s(const void* p) {
    uint32_t a;
    asm("{ .reg .u64 t; cvta.to.shared.u64 t, %1; cvt.u32.u64 %0, t; }"
        : "=r"(a) : "l"(p));
    return a;
}

__device__ __forceinline__ void ldsm4(uint32_t r[4], uint32_t addr) {
    asm volatile("ldmatrix.sync.aligned.m8n8.x4.shared.b16 {%0,%1,%2,%3}, [%4];"
                 : "=r"(r[0]), "=r"(r[1]), "=r"(r[2]), "=r"(r[3]) : "r"(addr));
}

__device__ __forceinline__ void ldsm4t(uint32_t r[4], uint32_t addr) {
    asm volatile("ldmatrix.sync.aligned.m8n8.x4.trans.shared.b16 {%0,%1,%2,%3}, [%4];"
                 : "=r"(r[0]), "=r"(r[1]), "=r"(r[2]), "=r"(r[3]) : "r"(addr));
}

__device__ __forceinline__ void mma16816(float d[4], const uint32_t a[4],
                                         const uint32_t b[2]) {
    asm volatile(
        "mma.sync.aligned.m16n8k16.row.col.f32.f16.f16.f32 "
        "{%0,%1,%2,%3}, {%4,%5,%6,%7}, {%8,%9}, {%0,%1,%2,%3};"
        : "+f"(d[0]), "+f"(d[1]), "+f"(d[2]), "+f"(d[3])
        : "r"(a[0]), "r"(a[1]), "r"(a[2]), "r"(a[3]), "r"(b[0]), "r"(b[1]));
}

__device__ __forceinline__ uint32_t packh2(float a, float b) {
    __half2 h = __floats2half2_rn(a, b);
    return *reinterpret_cast<uint32_t*>(&h);
}

// ---------------------------------------------------------------------------
__global__ void __launch_bounds__(256, 1)
fa2_hmma_kernel(const float* __restrict__ Qg, const float* __restrict__ Kg,
                const float* __restrict__ Vg, float* __restrict__ Og)
{
    extern __shared__ __half sm[];
    const uint32_t sb = cvta_s(sm);
    const int tid  = threadIdx.x;
    const int w    = tid >> 5;
    const int lane = tid & 31;
    const int g    = lane >> 2;    // row group 0..7
    const int c    = lane & 3;     // col pair 0..3
    const int bh   = blockIdx.x;
    const int qt   = 15 - (int)blockIdx.y;        // heavy q-tiles first
    const size_t base = (size_t)bh * SEQ * DH;
    const int qr0  = qt * 128;

    // ldmatrix per-lane address components
    const int a_row  = 16 * w + (lane & 7) + ((lane >> 3) & 1) * 8;
    const int a_col8 = (lane >> 4) * 8;
    const int bk_rowi = (lane & 7) + (lane >> 4) * 8;
    const int bk_col8 = ((lane >> 3) & 1) * 8;
    const int bv_rowi = (lane & 7) + ((lane >> 3) & 1) * 8;
    const int bv_col8 = (lane >> 4) * 8;

    // per-thread K/V load coordinates (8 float4 rows each, coalesced)
    const int ld_row = tid >> 5;          // 0..7 base row, step 8
    const int ld_c4  = tid & 31;          // float4 index within 128-d row

    // ---- prologue: Q tile -> split fp16 SMEM (pre-scaled) ------------------
    #pragma unroll
    for (int i = 0; i < 16; i++) {
        int idx = tid + i * 256;
        int row = idx >> 5, c4 = idx & 31;
        float4 v = *(const float4*)(Qg + base + (size_t)(qr0 + row) * DH + 4 * c4);
        v.x *= SCALE; v.y *= SCALE; v.z *= SCALE; v.w *= SCALE;
        __half hx = __float2half_rn(v.x), hy = __float2half_rn(v.y);
        __half hz = __float2half_rn(v.z), hw = __float2half_rn(v.w);
        uint32_t p = row * LDH + 4 * c4;
        *(__half2*)&sm[QHI_OFF + p]     = __halves2half2(hx, hy);
        *(__half2*)&sm[QHI_OFF + p + 2] = __halves2half2(hz, hw);
        *(__half2*)&sm[QLO_OFF + p] =
            __halves2half2(__float2half_rn(v.x - __half2float(hx)),
                           __float2half_rn(v.y - __half2float(hy)));
        *(__half2*)&sm[QLO_OFF + p + 2] =
            __halves2half2(__float2half_rn(v.z - __half2float(hz)),
                           __float2half_rn(v.w - __half2float(hw)));
    }

    const int nkt = 2 * (qt + 1);

    // ---- preload K/V tile 0 into stage 0 -----------------------------------
    {
        #pragma unroll
        for (int i = 0; i < 8; i++) {
            int row = ld_row + 8 * i;
            size_t goff = base + (size_t)row * DH + 4 * ld_c4;
            float4 kv = *(const float4*)(Kg + goff);
            float4 vv = *(const float4*)(Vg + goff);
            uint32_t p = row * LDH + 4 * ld_c4;
            *(__half2*)&sm[KHI_OFF + p]     = __floats2half2_rn(kv.x, kv.y);
            *(__half2*)&sm[KHI_OFF + p + 2] = __floats2half2_rn(kv.z, kv.w);
            *(__half2*)&sm[VHI_OFF + p]     = __floats2half2_rn(vv.x, vv.y);
            *(__half2*)&sm[VHI_OFF + p + 2] = __floats2half2_rn(vv.z, vv.w);
        }
    }

    float O_[16][4];
    #pragma unroll
    for (int n = 0; n < 16; n++)
        #pragma unroll
        for (int e = 0; e < 4; e++) O_[n][e] = 0.0f;
    float mA = -1e30f, mB = -1e30f, lA = 0.0f, lB = 0.0f;

    __syncthreads();

    for (int j = 0; j < nkt; j++) {
        const uint32_t kbuf = KHI_OFF + (uint32_t)(j & 1) * 64 * LDH;
        const uint32_t vbuf = VHI_OFF + (uint32_t)(j & 1) * 64 * LDH;

        // ---- prefetch tile j+1 into the other stage (overlaps with compute
        //      of tile j across warps; buffer was freed by last iter's sync)
        if (j + 1 < nkt) {
            const uint32_t kn = KHI_OFF + (uint32_t)((j + 1) & 1) * 64 * LDH;
            const uint32_t vn = VHI_OFF + (uint32_t)((j + 1) & 1) * 64 * LDH;
            #pragma unroll
            for (int i = 0; i < 8; i++) {
                int row = ld_row + 8 * i;
                size_t goff = base + (size_t)(64 * (j + 1) + row) * DH + 4 * ld_c4;
                float4 kv = *(const float4*)(Kg + goff);
                float4 vv = *(const float4*)(Vg + goff);
                uint32_t p = row * LDH + 4 * ld_c4;
                *(__half2*)&sm[kn + p]     = __floats2half2_rn(kv.x, kv.y);
                *(__half2*)&sm[kn + p + 2] = __floats2half2_rn(kv.z, kv.w);
                *(__half2*)&sm[vn + p]     = __floats2half2_rn(vv.x, vv.y);
                *(__half2*)&sm[vn + p + 2] = __floats2half2_rn(vv.z, vv.w);
            }
        }

        // ---- S = Q K^T  (2-pass: Qhi*K + Qlo*K) ----------------------------
        float S_[8][4];
        #pragma unroll
        for (int n = 0; n < 8; n++)
            #pragma unroll
            for (int e = 0; e < 4; e++) S_[n][e] = 0.0f;

        #pragma unroll
        for (int s = 0; s < 8; s++) {
            uint32_t qh[4], ql[4];
            uint32_t qa = sb + 2u * (uint32_t)(a_row * LDH + 16 * s + a_col8);
            ldsm4(qh, qa + 2u * QHI_OFF);
            ldsm4(ql, qa + 2u * QLO_OFF);
            #pragma unroll
            for (int t = 0; t < 4; t++) {
                uint32_t bhh[4];
                uint32_t ka = sb + 2u * (uint32_t)(kbuf + (16 * t + bk_rowi) * LDH
                                                   + 16 * s + bk_col8);
                ldsm4(bhh, ka);
                mma16816(S_[2 * t],     qh, bhh);
                mma16816(S_[2 * t + 1], qh, bhh + 2);
                mma16816(S_[2 * t],     ql, bhh);
                mma16816(S_[2 * t + 1], ql, bhh + 2);
            }
        }

        // ---- causal mask (diagonal-overlap tiles only) ---------------------
        const int rowA = qr0 + 16 * w + g;
        const int rowB = rowA + 8;
        if (j >= 2 * qt) {
            int kb = 64 * j;
            #pragma unroll
            for (int n = 0; n < 8; n++) {
                #pragma unroll
                for (int e = 0; e < 2; e++) {
                    int key = kb + 8 * n + 2 * c + e;
                    if (key > rowA) S_[n][e]     = -1e30f;
                    if (key > rowB) S_[n][2 + e] = -1e30f;
                }
            }
        }

        // ---- online softmax (quad-local rows) ------------------------------
        float mtA = -1e30f, mtB = -1e30f;
        #pragma unroll
        for (int n = 0; n < 8; n++) {
            mtA = fmaxf(mtA, fmaxf(S_[n][0], S_[n][1]));
            mtB = fmaxf(mtB, fmaxf(S_[n][2], S_[n][3]));
        }
        mtA = fmaxf(mtA, __shfl_xor_sync(0xffffffffu, mtA, 1));
        mtA = fmaxf(mtA, __shfl_xor_sync(0xffffffffu, mtA, 2));
        mtB = fmaxf(mtB, __shfl_xor_sync(0xffffffffu, mtB, 1));
        mtB = fmaxf(mtB, __shfl_xor_sync(0xffffffffu, mtB, 2));

        float mnA = fmaxf(mA, mtA), mnB = fmaxf(mB, mtB);
        float corrA = __expf(mA - mnA), corrB = __expf(mB - mnB);

        float sA = 0.0f, sB = 0.0f;
        #pragma unroll
        for (int n = 0; n < 8; n++) {
            S_[n][0] = __expf(S_[n][0] - mnA);
            S_[n][1] = __expf(S_[n][1] - mnA);
            S_[n][2] = __expf(S_[n][2] - mnB);
            S_[n][3] = __expf(S_[n][3] - mnB);
            sA += S_[n][0] + S_[n][1];
            sB += S_[n][2] + S_[n][3];
        }
        sA += __shfl_xor_sync(0xffffffffu, sA, 1);
        sA += __shfl_xor_sync(0xffffffffu, sA, 2);
        sB += __shfl_xor_sync(0xffffffffu, sB, 1);
        sB += __shfl_xor_sync(0xffffffffu, sB, 2);

        lA = lA * corrA + sA;  mA = mnA;
        lB = lB * corrB + sB;  mB = mnB;

        #pragma unroll
        for (int n = 0; n < 16; n++) {
            O_[n][0] *= corrA; O_[n][1] *= corrA;
            O_[n][2] *= corrB; O_[n][3] *= corrB;
        }

        // ---- P: C-layout -> split A-fragments ------------------------------
        uint32_t ph[4][4], pl[4][4];
        #pragma unroll
        for (int s = 0; s < 4; s++) {
            #pragma unroll
            for (int half_ : {0, 1}) {
                const float* src = S_[2 * s + half_];
                __half h0 = __float2half_rn(src[0]), h1 = __float2half_rn(src[1]);
                __half h2 = __float2half_rn(src[2]), h3 = __float2half_rn(src[3]);
                ph[s][2 * half_]     = packh2(__half2float(h0), __half2float(h1));
                ph[s][2 * half_ + 1] = packh2(__half2float(h2), __half2float(h3));
                pl[s][2 * half_]     = packh2(src[0] - __half2float(h0),
                                              src[1] - __half2float(h1));
                pl[s][2 * half_ + 1] = packh2(src[2] - __half2float(h2),
                                              src[3] - __half2float(h3));
            }
        }

        // ---- O += P V  (2-pass: Phi*V + Plo*V) -----------------------------
        #pragma unroll
        for (int s = 0; s < 4; s++) {
            #pragma unroll
            for (int t = 0; t < 8; t++) {
                uint32_t vh[4];
                uint32_t va = sb + 2u * (uint32_t)(vbuf + (16 * s + bv_rowi) * LDH
                                                   + 16 * t + bv_col8);
                ldsm4t(vh, va);
                mma16816(O_[2 * t],     ph[s], vh);
                mma16816(O_[2 * t + 1], ph[s], vh + 2);
                mma16816(O_[2 * t],     pl[s], vh);
                mma16816(O_[2 * t + 1], pl[s], vh + 2);
            }
        }

        __syncthreads();   // publish prefetched tile j+1; free buffer j
    }

    // ---- epilogue: O /= l, store fp32 -------------------------------------
    {
        float iA = 1.0f / lA, iB = 1.0f / lB;
        const int rowA = qr0 + 16 * w + g;
        float* oA = Og + base + (size_t)rowA * DH;
        float* oB = oA + 8 * DH;
        #pragma unroll
        for (int n = 0; n < 16; n++) {
            *(float2*)(oA + 8 * n + 2 * c) =
                make_float2(O_[n][0] * iA, O_[n][1] * iA);
            *(float2*)(oB + 8 * n + 2 * c) =
                make_float2(O_[n][2] * iB, O_[n][3] * iB);
        }
    }
}

// ---------------------------------------------------------------------------
extern "C" void kernel_launch(void* const* d_in, const int* in_sizes, int n_in,
                              void* d_out, int out_size) {
    const float* Q = (const float*)d_in[0];
    const float* K = (const float*)d_in[1];
    const float* V = (const float*)d_in[2];
    // d_in[3] = causal mask (known tril) — applied analytically in-kernel.
    float* O = (float*)d_out;

    cudaFuncSetAttribute(fa2_hmma_kernel,
                         cudaFuncAttributeMaxDynamicSharedMemorySize, SMEM_BYTES);

    dim3 grid(64, 16, 1);
    fa2_hmma_kernel<<<grid, 256, SMEM_BYTES>>>(Q, K, V, O);
}